// round 5
// baseline (speedup 1.0000x reference)
#include <cuda_runtime.h>
#include <cuda_fp16.h>
#include <cstdint>
#include <cstddef>

#define NB 16
#define NP 4096
#define NS 1024
#define NK 16
#define NKC 24
#define NF 256
#define NO 512
#define NPTS (NB*NP)
#define NQ   (NB*NS)
#define SEG  4
#define PSEG (NP/SEG)
#define KAUG 512

#define POS_INF __int_as_float(0x7f800000)
#define NEG_INF __int_as_float(0xff800000)

__device__ float  g_h[(size_t)NPTS * NO];
__device__ float  g_hn[NPTS];
__device__ __half g_xsplit[(size_t)NPTS * KAUG];   // per point: [hi(256)|lo(256)]
__device__ __half g_wsplit[(size_t)NO * KAUG];     // per out-feature n: K-major [hi|lo]
__device__ int    g_fps[NQ];
__device__ float  g_part[2 * 128 * NO];
__device__ float  g_a[NO];
__device__ float  g_c[NO];
__device__ int    g_knni[(size_t)NQ * SEG * NKC];  // candidate indices
__device__ int    g_nn[(size_t)NQ * NK];

// ---------------- helpers ----------------
__device__ __forceinline__ uint32_t smem_u32(const void* p) {
    uint32_t a;
    asm("{ .reg .u64 t; cvta.to.shared.u64 t, %1; cvt.u32.u64 %0, t; }" : "=r"(a) : "l"(p));
    return a;
}
__device__ __forceinline__ void cp16(uint32_t d, const void* s) {
    asm volatile("cp.async.cg.shared.global [%0], [%1], 16;" :: "r"(d), "l"(s) : "memory");
}
#define CP_COMMIT() asm volatile("cp.async.commit_group;" ::: "memory")
#define CP_WAIT1()  asm volatile("cp.async.wait_group 1;" ::: "memory")
#define CP_WAIT0()  asm volatile("cp.async.wait_group 0;" ::: "memory")
#define MMA16816(c, a, b) \
    asm volatile("mma.sync.aligned.m16n8k16.row.col.f32.f16.f16.f32 " \
        "{%0,%1,%2,%3}, {%4,%5,%6,%7}, {%8,%9}, {%0,%1,%2,%3};" \
        : "+f"((c)[0]), "+f"((c)[1]), "+f"((c)[2]), "+f"((c)[3]) \
        : "r"((a)[0]), "r"((a)[1]), "r"((a)[2]), "r"((a)[3]), "r"((b)[0]), "r"((b)[1]))

// 3-term split chunk remap over K'=768 (12 chunks of 64 halves):
// c 0-3: hi.hi   c 4-7: hi(A).lo(B)   c 8-11: lo(A).hi(B)
__device__ __forceinline__ int a_src(int c) { return (c & 3) + (c >= 8 ? 4 : 0); }
__device__ __forceinline__ int b_src(int c) { return (c & 3) + ((c >= 4 && c < 8) ? 4 : 0); }

// SMEM chunk buffer geometry: rows pitch 72 halves (144B) -> conflict-free frag loads
#define APITCH 72
#define CH_BYTES 18432            // 128 rows * 144B
#define BUF_BYTES (2*CH_BYTES)    // A + B
#define OFF_SC   (2*BUF_BYTES)                 // 73728
#define OFF_HN   (OFF_SC + 128*129*4)          // 139776
#define OFF_TOPV (OFF_HN + 512)                // 140288
#define OFF_TOPI (OFF_TOPV + 128*NKC*4)        // 152576
#define KNN_SMEM (OFF_TOPI + 128*NKC*4)        // 164864
#define MLP_SMEM (2*BUF_BYTES)                 // 73728

// ===================== FPS (bit-exact vs reference) =====================
__global__ __launch_bounds__(512) void fps_kernel(const float* __restrict__ positions,
                                                  const int* __restrict__ batch,
                                                  float* __restrict__ out_pos,
                                                  float* __restrict__ out_batch) {
    extern __shared__ float sm[];
    float* spos  = sm;
    int*   sel   = (int*)(spos + NP * 3);
    float* rv    = (float*)(sel + NS);
    int*   ri    = (int*)(rv + 16);
    int*   slast = ri + 16;
    const int cloud = blockIdx.x, tid = threadIdx.x;
    const float* pos = positions + (size_t)cloud * NP * 3;
    for (int i = tid; i < NP * 3; i += 512) spos[i] = pos[i];
    __syncthreads();
    float px[8], py[8], pz[8], md[8];
#pragma unroll
    for (int j = 0; j < 8; j++) {
        int pt = tid + j * 512;
        px[j] = spos[pt * 3]; py[j] = spos[pt * 3 + 1]; pz[j] = spos[pt * 3 + 2];
        md[j] = POS_INF;
    }
    if (tid == 0) sel[0] = 0;
    int last = 0;
    const int lane = tid & 31, warp = tid >> 5;
    for (int it = 1; it < NS; it++) {
        float lx = spos[last * 3], ly = spos[last * 3 + 1], lz = spos[last * 3 + 2];
        float bv = NEG_INF; int bi = 0x7fffffff;
#pragma unroll
        for (int j = 0; j < 8; j++) {
            float dx = px[j] - lx, dy = py[j] - ly, dz = pz[j] - lz;
            float d = __fadd_rn(__fadd_rn(__fmul_rn(dx, dx), __fmul_rn(dy, dy)), __fmul_rn(dz, dz));
            float m = fminf(md[j], d);
            md[j] = m;
            if (m > bv) { bv = m; bi = tid + j * 512; }
        }
#pragma unroll
        for (int off = 16; off > 0; off >>= 1) {
            float ov = __shfl_down_sync(0xffffffffu, bv, off);
            int   oi = __shfl_down_sync(0xffffffffu, bi, off);
            if (ov > bv || (ov == bv && oi < bi)) { bv = ov; bi = oi; }
        }
        if (lane == 0) { rv[warp] = bv; ri[warp] = bi; }
        __syncthreads();
        if (warp == 0) {
            float v = (lane < 16) ? rv[lane] : NEG_INF;
            int b = (lane < 16) ? ri[lane] : 0x7fffffff;
#pragma unroll
            for (int off = 8; off > 0; off >>= 1) {
                float ov = __shfl_down_sync(0xffffffffu, v, off);
                int   oi = __shfl_down_sync(0xffffffffu, b, off);
                if (ov > v || (ov == v && oi < b)) { v = ov; b = oi; }
            }
            if (lane == 0) { sel[it] = b; slast[0] = b; }
        }
        __syncthreads();
        last = slast[0];
    }
    for (int s = tid; s < NS; s += 512) {
        int loc = sel[s], g = cloud * NP + loc, oq = cloud * NS + s;
        g_fps[oq] = g;
        out_pos[oq * 3 + 0] = spos[loc * 3 + 0];
        out_pos[oq * 3 + 1] = spos[loc * 3 + 1];
        out_pos[oq * 3 + 2] = spos[loc * 3 + 2];
        out_batch[oq] = (float)batch[g];
    }
}

// ===================== fp16 hi/lo splits =====================
__global__ __launch_bounds__(256) void split_kernel(const float* __restrict__ feat) {
    size_t i = (size_t)blockIdx.x * 256 + threadIdx.x;  // 4 floats each
    float4 f = ((const float4*)feat)[i];
    size_t pt = i / (NF / 4);
    int k4 = (int)(i % (NF / 4)) * 4;
    const float* fv = &f.x;
    __half h[4], l[4];
#pragma unroll
    for (int j = 0; j < 4; j++) {
        h[j] = __float2half_rn(fv[j]);
        l[j] = __float2half_rn(fv[j] - __half2float(h[j]));
    }
    __half2* hp = (__half2*)(g_xsplit + pt * KAUG + k4);
    __half2* lp = (__half2*)(g_xsplit + pt * KAUG + 256 + k4);
    hp[0] = __halves2half2(h[0], h[1]); hp[1] = __halves2half2(h[2], h[3]);
    lp[0] = __halves2half2(l[0], l[1]); lp[1] = __halves2half2(l[2], l[3]);
}

__global__ __launch_bounds__(256) void wsplit_kernel(const float* __restrict__ W) {
    int idx = blockIdx.x * 256 + threadIdx.x;  // NO*KAUG
    int n = idx >> 9, kk = idx & 511, k = kk & 255;
    float v = W[(size_t)k * NO + n];
    __half h = __float2half_rn(v);
    g_wsplit[(size_t)n * KAUG + kk] = (kk < 256) ? h : __float2half_rn(v - __half2float(h));
}

__global__ __launch_bounds__(128) void xnorm_kernel(const float* __restrict__ feat) {
    int row = blockIdx.x * 4 + (threadIdx.x >> 5), lane = threadIdx.x & 31;
    const float* f = feat + (size_t)row * NF;
    float s = 0.f;
#pragma unroll
    for (int i = 0; i < NF / 32; i++) { float v = f[lane + 32 * i]; s = fmaf(v, v, s); }
#pragma unroll
    for (int off = 16; off > 0; off >>= 1) s += __shfl_down_sync(0xffffffffu, s, off);
    if (lane == 0) g_hn[row] = 0.5f * s;
}

// ===================== shared mma tile computation =====================
// 8 warps as 2(m) x 4(n); warp tile 64x32; frags via direct half2 LDS (pitch 72).
__device__ __forceinline__ void mma_chunk(const __half* As, const __half* Bs,
                                          int wm, int wn, int grp, int qp,
                                          float acc[4][4][4]) {
#pragma unroll
    for (int kk = 0; kk < 64; kk += 16) {
        uint32_t a[4][4], b[4][2];
#pragma unroll
        for (int i = 0; i < 4; i++) {
            int r0 = wm * 64 + i * 16 + grp;
            const __half* p0 = As + r0 * APITCH + kk + qp * 2;
            const __half* p1 = As + (r0 + 8) * APITCH + kk + qp * 2;
            a[i][0] = *(const uint32_t*)p0;
            a[i][1] = *(const uint32_t*)p1;
            a[i][2] = *(const uint32_t*)(p0 + 8);
            a[i][3] = *(const uint32_t*)(p1 + 8);
        }
#pragma unroll
        for (int j = 0; j < 4; j++) {
            int n0 = wn * 32 + j * 8 + grp;
            const __half* p = Bs + n0 * APITCH + kk + qp * 2;
            b[j][0] = *(const uint32_t*)p;
            b[j][1] = *(const uint32_t*)(p + 8);
        }
#pragma unroll
        for (int i = 0; i < 4; i++)
#pragma unroll
            for (int j = 0; j < 4; j++)
                MMA16816(acc[i][j], a[i], b[j]);
    }
}

// ===================== MLP GEMM: h = X W + b =====================
__global__ __launch_bounds__(256, 2) void mlp_mma_kernel(const float* __restrict__ bias) {
    extern __shared__ __align__(16) char smc[];
    const uint32_t sb = smem_u32(smc);
    const int tid = threadIdx.x, wid = tid >> 5, lane = tid & 31;
    const int wm = wid >> 2, wn = wid & 3, grp = lane >> 2, qp = lane & 3;
    const int nbase = blockIdx.x * 128, mbase = blockIdx.y * 128;
    const int lr = tid >> 3, lv = tid & 7;

    float acc[4][4][4];
#pragma unroll
    for (int i = 0; i < 4; i++)
#pragma unroll
        for (int j = 0; j < 4; j++)
#pragma unroll
            for (int v = 0; v < 4; v++) acc[i][j][v] = 0.f;

    {
        int asrc = a_src(0), bsrc = b_src(0);
#pragma unroll
        for (int i = 0; i < 4; i++) {
            int r = i * 32 + lr;
            cp16(sb + r * 144 + lv * 16,
                 g_xsplit + (size_t)(mbase + r) * KAUG + asrc * 64 + lv * 8);
            cp16(sb + CH_BYTES + r * 144 + lv * 16,
                 g_wsplit + (size_t)(nbase + r) * KAUG + bsrc * 64 + lv * 8);
        }
        CP_COMMIT();
    }
    for (int c = 0; c < 12; c++) {
        if (c < 11) {
            int nb = (c + 1) & 1;
            int asrc = a_src(c + 1), bsrc = b_src(c + 1);
#pragma unroll
            for (int i = 0; i < 4; i++) {
                int r = i * 32 + lr;
                cp16(sb + nb * BUF_BYTES + r * 144 + lv * 16,
                     g_xsplit + (size_t)(mbase + r) * KAUG + asrc * 64 + lv * 8);
                cp16(sb + nb * BUF_BYTES + CH_BYTES + r * 144 + lv * 16,
                     g_wsplit + (size_t)(nbase + r) * KAUG + bsrc * 64 + lv * 8);
            }
            CP_COMMIT();
            CP_WAIT1();
        } else {
            CP_WAIT0();
        }
        __syncthreads();
        const __half* As = (const __half*)(smc + (c & 1) * BUF_BYTES);
        mma_chunk(As, As + CH_BYTES / 2, wm, wn, grp, qp, acc);
        __syncthreads();
    }

#pragma unroll
    for (int i = 0; i < 4; i++) {
        int row = mbase + wm * 64 + i * 16 + grp;
#pragma unroll
        for (int j = 0; j < 4; j++) {
            int col = nbase + wn * 32 + j * 8 + qp * 2;
            float b0 = bias[col], b1 = bias[col + 1];
            float2 v0 = {acc[i][j][0] + b0, acc[i][j][1] + b1};
            float2 v1 = {acc[i][j][2] + b0, acc[i][j][3] + b1};
            *(float2*)&g_h[(size_t)row * NO + col] = v0;
            *(float2*)&g_h[(size_t)(row + 8) * NO + col] = v1;
        }
    }
}

// ===================== BN stats =====================
__global__ __launch_bounds__(512) void stats_partial_kernel() {
    int c = threadIdx.x, blk = blockIdx.x;
    float s = 0.f, s2 = 0.f;
    int r0 = blk * 512;
    for (int r = 0; r < 512; r++) {
        float v = g_h[(size_t)(r0 + r) * NO + c];
        s += v; s2 = fmaf(v, v, s2);
    }
    g_part[blk * NO + c] = s;
    g_part[128 * NO + blk * NO + c] = s2;
}
__global__ __launch_bounds__(512) void stats_final_kernel(const float* __restrict__ gamma,
                                                          const float* __restrict__ beta) {
    int c = threadIdx.x;
    float s = 0.f, s2 = 0.f;
    for (int b = 0; b < 128; b++) { s += g_part[b * NO + c]; s2 += g_part[128 * NO + b * NO + c]; }
    float inv = 1.0f / (float)NPTS;
    float mu = s * inv, var = s2 * inv - mu * mu;
    float a = gamma[c] * rsqrtf(var + 1e-5f);
    g_a[c] = a; g_c[c] = beta[c] - mu * a;
}

// ===================== KNN candidates: mma scores + approx top-24 ============
__global__ __launch_bounds__(256, 1) void knn_mma_kernel() {
    extern __shared__ __align__(16) char smc[];
    const uint32_t sb = smem_u32(smc);
    float* Sc   = (float*)(smc + OFF_SC);
    float* hn_s = (float*)(smc + OFF_HN);
    float* topv = (float*)(smc + OFF_TOPV);
    int*   topi = (int*)(smc + OFF_TOPI);

    const int tid = threadIdx.x, wid = tid >> 5, lane = tid & 31;
    const int wm = wid >> 2, wn = wid & 3, grp = lane >> 2, qp = lane & 3;
    const int qt = blockIdx.x, sg = blockIdx.y, cloud = blockIdx.z;
    const int lr = tid >> 3, lv = tid & 7;

    int qr[4];
#pragma unroll
    for (int i = 0; i < 4; i++)
        qr[i] = g_fps[cloud * NS + qt * 128 + i * 32 + lr];

    if (tid < 128) {
#pragma unroll
        for (int r = 0; r < NKC; r++) {
            topv[tid * NKC + r] = NEG_INF;
            topi[tid * NKC + r] = 0x7fffffff;
        }
    }
    const int xcloud = cloud * NP + sg * PSEG;

    for (int t = 0; t < PSEG / 128; t++) {
        const int xbase = xcloud + t * 128;
        if (tid < 128) hn_s[tid] = g_hn[xbase + tid];

        float acc[4][4][4];
#pragma unroll
        for (int i = 0; i < 4; i++)
#pragma unroll
            for (int j = 0; j < 4; j++)
#pragma unroll
                for (int v = 0; v < 4; v++) acc[i][j][v] = 0.f;

        {
            int asrc = a_src(0), bsrc = b_src(0);
#pragma unroll
            for (int i = 0; i < 4; i++) {
                int r = i * 32 + lr;
                cp16(sb + r * 144 + lv * 16,
                     g_xsplit + (size_t)qr[i] * KAUG + asrc * 64 + lv * 8);
                cp16(sb + CH_BYTES + r * 144 + lv * 16,
                     g_xsplit + (size_t)(xbase + r) * KAUG + bsrc * 64 + lv * 8);
            }
            CP_COMMIT();
        }
        for (int c = 0; c < 12; c++) {
            if (c < 11) {
                int nb = (c + 1) & 1;
                int asrc = a_src(c + 1), bsrc = b_src(c + 1);
#pragma unroll
                for (int i = 0; i < 4; i++) {
                    int r = i * 32 + lr;
                    cp16(sb + nb * BUF_BYTES + r * 144 + lv * 16,
                         g_xsplit + (size_t)qr[i] * KAUG + asrc * 64 + lv * 8);
                    cp16(sb + nb * BUF_BYTES + CH_BYTES + r * 144 + lv * 16,
                         g_xsplit + (size_t)(xbase + r) * KAUG + bsrc * 64 + lv * 8);
                }
                CP_COMMIT();
                CP_WAIT1();
            } else {
                CP_WAIT0();
            }
            __syncthreads();
            const __half* As = (const __half*)(smc + (c & 1) * BUF_BYTES);
            mma_chunk(As, As + CH_BYTES / 2, wm, wn, grp, qp, acc);
            __syncthreads();
        }

#pragma unroll
        for (int i = 0; i < 4; i++) {
            int row = wm * 64 + i * 16 + grp;
#pragma unroll
            for (int j = 0; j < 4; j++) {
                int col = wn * 32 + j * 8 + qp * 2;
                Sc[row * 129 + col]           = acc[i][j][0];
                Sc[row * 129 + col + 1]       = acc[i][j][1];
                Sc[(row + 8) * 129 + col]     = acc[i][j][2];
                Sc[(row + 8) * 129 + col + 1] = acc[i][j][3];
            }
        }
        __syncthreads();

        if (tid < 128) {
            const float* scr = Sc + tid * 129;
            float* tv = topv + tid * NKC;
            int*   ti = topi + tid * NKC;
            float th = tv[NKC - 1];
            int  thi = ti[NKC - 1];
            for (int p = 0; p < 128; p++) {
                float s = scr[p] - hn_s[p];
                int gi = xbase + p;
                if (s > th || (s == th && gi < thi)) {
                    int r = NKC - 1;
                    while (r > 0) {
                        float pv = tv[r - 1];
                        int   pi = ti[r - 1];
                        if (s > pv || (s == pv && gi < pi)) {
                            tv[r] = pv; ti[r] = pi; r--;
                        } else break;
                    }
                    tv[r] = s; ti[r] = gi;
                    th = tv[NKC - 1]; thi = ti[NKC - 1];
                }
            }
        }
        __syncthreads();
    }

    if (tid < 128) {
        int q = cloud * NS + qt * 128 + tid;
#pragma unroll
        for (int r = 0; r < NKC; r++)
            g_knni[((size_t)q * SEG + sg) * NKC + r] = topi[tid * NKC + r];
    }
}

// ===================== exact rescore of 96 candidates -> top-16 ==============
// Reproduces round-1 arithmetic exactly: ascending-k fmaf dot, s -= 0.5|x|^2,
// ordering by (score desc, index asc).
__global__ __launch_bounds__(128) void rescore_kernel(const float* __restrict__ feat) {
    __shared__ float q[NF];
    __shared__ float sv[SEG * NKC];
    __shared__ int   si[SEG * NKC];
    const int qi = blockIdx.x, tid = threadIdx.x;
    const int qg = g_fps[qi];
    q[tid]       = feat[(size_t)qg * NF + tid];
    q[tid + 128] = feat[(size_t)qg * NF + 128 + tid];
    __syncthreads();

    if (tid < SEG * NKC) {
        int gi = g_knni[(size_t)qi * SEG * NKC + tid];
        const float4* x = (const float4*)(feat + (size_t)gi * NF);
        float s = 0.f;
#pragma unroll 8
        for (int k4 = 0; k4 < NF / 4; k4++) {
            float4 xv = x[k4];
            s = fmaf(q[k4 * 4 + 0], xv.x, s);
            s = fmaf(q[k4 * 4 + 1], xv.y, s);
            s = fmaf(q[k4 * 4 + 2], xv.z, s);
            s = fmaf(q[k4 * 4 + 3], xv.w, s);
        }
        s -= g_hn[gi];
        sv[tid] = s;
        si[tid] = gi;
    }
    __syncthreads();

    if (tid < SEG * NKC) {
        float s = sv[tid];
        int gi = si[tid];
        int cnt = 0;
        for (int j = 0; j < SEG * NKC; j++) {
            float vj = sv[j];
            cnt += (vj > s || (vj == s && si[j] < gi)) ? 1 : 0;
        }
        if (cnt < NK) g_nn[(size_t)qi * NK + cnt] = gi;
    }
}

// ===================== gather + max-pool + BN + ReLU =========================
__global__ __launch_bounds__(128) void gather_kernel(float* __restrict__ out) {
    __shared__ int nn[NK];
    const int q = blockIdx.x, tid = threadIdx.x;
    if (tid < NK) nn[tid] = g_nn[(size_t)q * NK + tid];
    __syncthreads();
    float mx[4] = {NEG_INF, NEG_INF, NEG_INF, NEG_INF};
    float mn[4] = {POS_INF, POS_INF, POS_INF, POS_INF};
#pragma unroll
    for (int n = 0; n < NK; n++) {
        const float* hp = g_h + (size_t)nn[n] * NO;
#pragma unroll
        for (int j = 0; j < 4; j++) {
            float v = hp[tid + j * 128];
            mx[j] = fmaxf(mx[j], v); mn[j] = fminf(mn[j], v);
        }
    }
    float* op = out + (size_t)q * NO;
#pragma unroll
    for (int j = 0; j < 4; j++) {
        int c = tid + j * 128;
        float a = g_a[c], cc = g_c[c];
        float o = fmaxf(fmaf(a, mx[j], cc), fmaf(a, mn[j], cc));
        op[c] = fmaxf(o, 0.0f);
    }
}

// ===================== launch =====================
#define FPS_SMEM ((NP * 3 + NS + 16 + 16 + 1) * 4)

extern "C" void kernel_launch(void* const* d_in, const int* in_sizes, int n_in,
                              void* d_out, int out_size) {
    (void)in_sizes; (void)n_in; (void)out_size;
    const float* features  = (const float*)d_in[0];
    const float* positions = (const float*)d_in[1];
    const int*   batch     = (const int*)d_in[2];
    const float* W         = (const float*)d_in[3];
    const float* bias      = (const float*)d_in[4];
    const float* gamma     = (const float*)d_in[5];
    const float* beta      = (const float*)d_in[6];

    float* out       = (float*)d_out;
    float* out_feat  = out;
    float* out_pos   = out + (size_t)NQ * NO;
    float* out_batch = out_pos + (size_t)NQ * 3;

    cudaFuncSetAttribute(fps_kernel, cudaFuncAttributeMaxDynamicSharedMemorySize, FPS_SMEM);
    cudaFuncSetAttribute(mlp_mma_kernel, cudaFuncAttributeMaxDynamicSharedMemorySize, MLP_SMEM);
    cudaFuncSetAttribute(knn_mma_kernel, cudaFuncAttributeMaxDynamicSharedMemorySize, KNN_SMEM);

    fps_kernel<<<NB, 512, FPS_SMEM>>>(positions, batch, out_pos, out_batch);
    split_kernel<<<NPTS * (NF / 4) / 256, 256>>>(features);
    wsplit_kernel<<<NO * KAUG / 256, 256>>>(W);
    xnorm_kernel<<<NPTS / 4, 128>>>(features);
    mlp_mma_kernel<<<dim3(4, NPTS / 128), 256, MLP_SMEM>>>(bias);
    stats_partial_kernel<<<128, 512>>>();
    stats_final_kernel<<<1, 512>>>(gamma, beta);
    knn_mma_kernel<<<dim3(8, SEG, NB), 256, KNN_SMEM>>>();
    rescore_kernel<<<NQ, 128>>>(features);
    gather_kernel<<<NQ, 128>>>(out_feat);
}

// round 6
// speedup vs baseline: 1.2097x; 1.2097x over previous
#include <cuda_runtime.h>
#include <cstdint>
#include <cstddef>

// Problem constants
#define NB 16
#define NP 4096
#define NS 1024
#define NK 16
#define NF 256
#define NO 512
#define NPTS (NB*NP)   // 65536
#define NQ   (NB*NS)   // 16384
#define SEG  4
#define PSEG (NP/SEG)  // 1024

#define POS_INF __int_as_float(0x7f800000)
#define NEG_INF __int_as_float(0xff800000)

typedef unsigned long long u64;

// ------------------------- scratch (static device globals) -------------------
__device__ float g_h[(size_t)NPTS * NO];      // 128MB: h = XW + b
__device__ float g_hn[NPTS];                  // 0.5*|x|^2 per point (feature space)
__device__ int   g_fps[NQ];                   // global fps indices
__device__ float g_part[2 * 128 * NO];        // column partial sums / sumsq
__device__ float g_a[NO];                     // BN scale  a = gamma*rsqrt(var+eps)
__device__ float g_c[NO];                     // BN shift  c = beta - mu*a
__device__ float g_knnv[(size_t)NQ * SEG * NK];
__device__ int   g_knni[(size_t)NQ * SEG * NK];
__device__ int   g_nn[(size_t)NQ * NK];

// ------------------------- f32x2 packed helpers ------------------------------
// Each half of an f32x2 fma is rounded exactly like a scalar FFMA, so keeping
// the same k-order keeps results bit-identical to the scalar round-1 kernel.
__device__ __forceinline__ u64 dup2(float x) {
    u64 r;
    uint32_t b = __float_as_uint(x);
    asm("mov.b64 %0, {%1, %1};" : "=l"(r) : "r"(b));
    return r;
}
#define FMA2(acc, a, b) \
    asm("fma.rn.f32x2 %0, %1, %2, %0;" : "+l"(acc) : "l"(a), "l"(b))
__device__ __forceinline__ float2 unpack2(u64 v) {
    float2 r;
    asm("mov.b64 {%0, %1}, %2;" : "=f"(r.x), "=f"(r.y) : "l"(v));
    return r;
}

// ------------------------- FPS: one block per cloud --------------------------
// Bit-exact vs jax reference: d = (dx*dx + dy*dy) + dz*dz with RN mul/add
// (no FMA contraction), fminf accumulation, argmax with first-index tiebreak.
__global__ __launch_bounds__(512) void fps_kernel(const float* __restrict__ positions,
                                                  const int* __restrict__ batch,
                                                  float* __restrict__ out_pos,
                                                  float* __restrict__ out_batch) {
    extern __shared__ float sm[];
    float* spos  = sm;                          // NP*3 floats
    int*   sel   = (int*)(spos + NP * 3);       // NS
    float* rv    = (float*)(sel + NS);          // 16
    int*   ri    = (int*)(rv + 16);             // 16
    int*   slast = ri + 16;                     // 1

    const int cloud = blockIdx.x;
    const int tid = threadIdx.x;
    const float* pos = positions + (size_t)cloud * NP * 3;

    for (int i = tid; i < NP * 3; i += 512) spos[i] = pos[i];
    __syncthreads();

    float px[8], py[8], pz[8], md[8];
#pragma unroll
    for (int j = 0; j < 8; j++) {
        int pt = tid + j * 512;
        px[j] = spos[pt * 3 + 0];
        py[j] = spos[pt * 3 + 1];
        pz[j] = spos[pt * 3 + 2];
        md[j] = POS_INF;
    }
    if (tid == 0) sel[0] = 0;
    int last = 0;
    const int lane = tid & 31, warp = tid >> 5;

    for (int it = 1; it < NS; it++) {
        float lx = spos[last * 3 + 0];
        float ly = spos[last * 3 + 1];
        float lz = spos[last * 3 + 2];
        float bv = NEG_INF;
        int bi = 0x7fffffff;
#pragma unroll
        for (int j = 0; j < 8; j++) {
            float dx = px[j] - lx, dy = py[j] - ly, dz = pz[j] - lz;
            float d = __fadd_rn(__fadd_rn(__fmul_rn(dx, dx), __fmul_rn(dy, dy)),
                                __fmul_rn(dz, dz));
            float m = fminf(md[j], d);
            md[j] = m;
            if (m > bv) { bv = m; bi = tid + j * 512; }
        }
#pragma unroll
        for (int off = 16; off > 0; off >>= 1) {
            float ov = __shfl_down_sync(0xffffffffu, bv, off);
            int   oi = __shfl_down_sync(0xffffffffu, bi, off);
            if (ov > bv || (ov == bv && oi < bi)) { bv = ov; bi = oi; }
        }
        if (lane == 0) { rv[warp] = bv; ri[warp] = bi; }
        __syncthreads();
        if (warp == 0) {
            float v = (lane < 16) ? rv[lane] : NEG_INF;
            int b = (lane < 16) ? ri[lane] : 0x7fffffff;
#pragma unroll
            for (int off = 8; off > 0; off >>= 1) {
                float ov = __shfl_down_sync(0xffffffffu, v, off);
                int   oi = __shfl_down_sync(0xffffffffu, b, off);
                if (ov > v || (ov == v && oi < b)) { v = ov; b = oi; }
            }
            if (lane == 0) { sel[it] = b; slast[0] = b; }
        }
        __syncthreads();
        last = slast[0];
    }

    for (int s = tid; s < NS; s += 512) {
        int loc = sel[s];
        int g = cloud * NP + loc;
        int oq = cloud * NS + s;
        g_fps[oq] = g;
        out_pos[oq * 3 + 0] = spos[loc * 3 + 0];
        out_pos[oq * 3 + 1] = spos[loc * 3 + 1];
        out_pos[oq * 3 + 2] = spos[loc * 3 + 2];
        out_batch[oq] = (float)batch[g];
    }
}

// ------------------------- 0.5*|x|^2 per point (feature space) ---------------
__global__ __launch_bounds__(128) void xnorm_kernel(const float* __restrict__ feat) {
    int row = blockIdx.x * 4 + (threadIdx.x >> 5);
    int lane = threadIdx.x & 31;
    const float* f = feat + (size_t)row * NF;
    float s = 0.f;
#pragma unroll
    for (int i = 0; i < NF / 32; i++) {
        float v = f[lane + 32 * i];
        s = fmaf(v, v, s);
    }
#pragma unroll
    for (int off = 16; off > 0; off >>= 1) s += __shfl_down_sync(0xffffffffu, s, off);
    if (lane == 0) g_hn[row] = 0.5f * s;
}

// ------------------------- SGEMM h = X*W + b  (f32x2, 128x128x8) -------------
__global__ __launch_bounds__(256) void gemm_h_kernel(const float* __restrict__ A,
                                                     const float* __restrict__ W,
                                                     const float* __restrict__ bias) {
    __shared__ float As[8][128];
    __shared__ float Bs[8][128];
    const int bx = blockIdx.x;  // 0..3   (N tiles)
    const int by = blockIdx.y;  // 0..511 (M tiles)
    const int tid = threadIdx.x;
    const int tx = tid & 15, ty = tid >> 4;
    const float* Ab = A + (size_t)by * 128 * NF;
    const int arow = tid >> 1, acol = (tid & 1) * 4;
    const int brow = tid >> 5, bcol = (tid & 31) * 4;

    u64 acc2[8][4];
#pragma unroll
    for (int i = 0; i < 8; i++)
#pragma unroll
        for (int jp = 0; jp < 4; jp++) acc2[i][jp] = 0ull;

    for (int kb = 0; kb < NF; kb += 8) {
        float4 av = *(const float4*)(Ab + (size_t)arow * NF + kb + acol);
        As[acol + 0][arow] = av.x;
        As[acol + 1][arow] = av.y;
        As[acol + 2][arow] = av.z;
        As[acol + 3][arow] = av.w;
        float4 bv = *(const float4*)(W + (size_t)(kb + brow) * NO + bx * 128 + bcol);
        *(float4*)&Bs[brow][bcol] = bv;
        __syncthreads();
#pragma unroll
        for (int k = 0; k < 8; k++) {
            float4 a0 = *(const float4*)&As[k][ty * 8];
            float4 a1 = *(const float4*)&As[k][ty * 8 + 4];
            const u64* bp = (const u64*)&Bs[k][tx * 8];
            u64 b2[4] = {bp[0], bp[1], bp[2], bp[3]};
            u64 ad[8] = {dup2(a0.x), dup2(a0.y), dup2(a0.z), dup2(a0.w),
                         dup2(a1.x), dup2(a1.y), dup2(a1.z), dup2(a1.w)};
#pragma unroll
            for (int i = 0; i < 8; i++)
#pragma unroll
                for (int jp = 0; jp < 4; jp++)
                    FMA2(acc2[i][jp], ad[i], b2[jp]);
        }
        __syncthreads();
    }

    const int ccol = bx * 128 + tx * 8;
    const int crow = by * 128 + ty * 8;
    float4 bb0 = *(const float4*)(bias + ccol);
    float4 bb1 = *(const float4*)(bias + ccol + 4);
#pragma unroll
    for (int i = 0; i < 8; i++) {
        float2 p0 = unpack2(acc2[i][0]), p1 = unpack2(acc2[i][1]);
        float2 p2 = unpack2(acc2[i][2]), p3 = unpack2(acc2[i][3]);
        float4 o0, o1;
        o0.x = p0.x + bb0.x; o0.y = p0.y + bb0.y;
        o0.z = p1.x + bb0.z; o0.w = p1.y + bb0.w;
        o1.x = p2.x + bb1.x; o1.y = p2.y + bb1.y;
        o1.z = p3.x + bb1.z; o1.w = p3.y + bb1.w;
        *(float4*)(g_h + (size_t)(crow + i) * NO + ccol) = o0;
        *(float4*)(g_h + (size_t)(crow + i) * NO + ccol + 4) = o1;
    }
}

// ------------------------- BN column stats (2-stage, deterministic) ----------
__global__ __launch_bounds__(512) void stats_partial_kernel() {
    int c = threadIdx.x;
    int blk = blockIdx.x;
    float s = 0.f, s2 = 0.f;
    int r0 = blk * 512;
    for (int r = 0; r < 512; r++) {
        float v = g_h[(size_t)(r0 + r) * NO + c];
        s += v;
        s2 = fmaf(v, v, s2);
    }
    g_part[blk * NO + c] = s;
    g_part[128 * NO + blk * NO + c] = s2;
}

__global__ __launch_bounds__(512) void stats_final_kernel(const float* __restrict__ gamma,
                                                          const float* __restrict__ beta) {
    int c = threadIdx.x;
    float s = 0.f, s2 = 0.f;
    for (int b = 0; b < 128; b++) {
        s  += g_part[b * NO + c];
        s2 += g_part[128 * NO + b * NO + c];
    }
    float inv = 1.0f / (float)NPTS;
    float mu  = s * inv;
    float var = s2 * inv - mu * mu;
    float a = gamma[c] * rsqrtf(var + 1e-5f);
    g_a[c] = a;
    g_c[c] = beta[c] - mu * a;
}

// ------------------------- fused KNN score-GEMM (f32x2) + top-16 -------------
// score = q.x - 0.5|x|^2  (maximize == minimize squared distance)
// grid: (8 query-tiles, 4 point-segments, 16 clouds); 256 thr; 128x128 tiles.
__global__ __launch_bounds__(256, 2) void knn_kernel(const float* __restrict__ feat) {
    extern __shared__ float sm[];
    float* Qs   = sm;                     // 8*128
    float* Xs   = Qs + 8 * 128;           // 8*128
    float* Sc   = Xs + 8 * 128;           // 128*129 (pitch 129: conflict-free col reads)
    float* hn   = Sc + 128 * 129;         // 128
    float* topv = hn + 128;               // 128*16
    int*   topi = (int*)(topv + 128 * 16);// 128*16
    int*   qrow = topi + 128 * 16;        // 128

    const int qt = blockIdx.x, sg = blockIdx.y, cloud = blockIdx.z;
    const int tid = threadIdx.x;
    const int tx = tid & 15, ty = tid >> 4;

    if (tid < 128) {
        qrow[tid] = g_fps[cloud * NS + qt * 128 + tid];
#pragma unroll
        for (int r = 0; r < NK; r++) {
            topv[tid * NK + r] = NEG_INF;
            topi[tid * NK + r] = 0x7fffffff;
        }
    }
    __syncthreads();

    const int arow = tid >> 1, acol = (tid & 1) * 4;
    const float* qptr = feat + (size_t)qrow[arow] * NF;
    const int xcloudbase = cloud * NP + sg * PSEG;

    for (int pt = 0; pt < PSEG; pt += 128) {
        const int xbase = xcloudbase + pt;
        if (tid < 128) hn[tid] = g_hn[xbase + tid];
        const float* xptr = feat + (size_t)(xbase + arow) * NF;

        u64 acc2[8][4];
#pragma unroll
        for (int i = 0; i < 8; i++)
#pragma unroll
            for (int jp = 0; jp < 4; jp++) acc2[i][jp] = 0ull;

        for (int kb = 0; kb < NF; kb += 8) {
            float4 qv = *(const float4*)(qptr + kb + acol);
            Qs[(acol + 0) * 128 + arow] = qv.x;
            Qs[(acol + 1) * 128 + arow] = qv.y;
            Qs[(acol + 2) * 128 + arow] = qv.z;
            Qs[(acol + 3) * 128 + arow] = qv.w;
            float4 xv = *(const float4*)(xptr + kb + acol);
            Xs[(acol + 0) * 128 + arow] = xv.x;
            Xs[(acol + 1) * 128 + arow] = xv.y;
            Xs[(acol + 2) * 128 + arow] = xv.z;
            Xs[(acol + 3) * 128 + arow] = xv.w;
            __syncthreads();
#pragma unroll
            for (int k = 0; k < 8; k++) {
                float4 a0 = *(const float4*)&Qs[k * 128 + ty * 8];
                float4 a1 = *(const float4*)&Qs[k * 128 + ty * 8 + 4];
                const u64* bp = (const u64*)&Xs[k * 128 + tx * 8];
                u64 b2[4] = {bp[0], bp[1], bp[2], bp[3]};
                u64 ad[8] = {dup2(a0.x), dup2(a0.y), dup2(a0.z), dup2(a0.w),
                             dup2(a1.x), dup2(a1.y), dup2(a1.z), dup2(a1.w)};
#pragma unroll
                for (int i = 0; i < 8; i++)
#pragma unroll
                    for (int jp = 0; jp < 4; jp++)
                        FMA2(acc2[i][jp], ad[i], b2[jp]);
            }
            __syncthreads();
        }

#pragma unroll
        for (int i = 0; i < 8; i++) {
#pragma unroll
            for (int jp = 0; jp < 4; jp++) {
                float2 p = unpack2(acc2[i][jp]);
                Sc[(ty * 8 + i) * 129 + tx * 8 + jp * 2]     = p.x;
                Sc[(ty * 8 + i) * 129 + tx * 8 + jp * 2 + 1] = p.y;
            }
        }
        __syncthreads();

        // running top-16 insertion (1 thread per query; threshold cached in regs)
        if (tid < 128) {
            const float* scr = Sc + tid * 129;
            float* tv = topv + tid * NK;
            int*   ti = topi + tid * NK;
            float th = tv[NK - 1];
            int  thi = ti[NK - 1];
            for (int p = 0; p < 128; p++) {
                float s = scr[p] - hn[p];
                int gi = xbase + p;
                if (s > th || (s == th && gi < thi)) {
                    int r = NK - 1;
                    while (r > 0) {
                        float pv = tv[r - 1];
                        int   pi = ti[r - 1];
                        if (s > pv || (s == pv && gi < pi)) {
                            tv[r] = pv; ti[r] = pi; r--;
                        } else break;
                    }
                    tv[r] = s; ti[r] = gi;
                    th = tv[NK - 1]; thi = ti[NK - 1];
                }
            }
        }
        __syncthreads();
    }

    if (tid < 128) {
        int q = cloud * NS + qt * 128 + tid;
#pragma unroll
        for (int r = 0; r < NK; r++) {
            g_knnv[((size_t)q * SEG + sg) * NK + r] = topv[tid * NK + r];
            g_knni[((size_t)q * SEG + sg) * NK + r] = topi[tid * NK + r];
        }
    }
}

// ------------------------- merge per-segment top-16 lists --------------------
__global__ __launch_bounds__(256) void merge_kernel() {
    int q = blockIdx.x * 256 + threadIdx.x;
    if (q >= NQ) return;
    const float* v  = g_knnv + (size_t)q * SEG * NK;
    const int*   ii = g_knni + (size_t)q * SEG * NK;
    unsigned long long used = 0ull;
    for (int r = 0; r < NK; r++) {
        float bv = NEG_INF;
        int bi = 0x7fffffff, bs = 0;
        for (int j = 0; j < SEG * NK; j++) {
            if ((used >> j) & 1ull) continue;
            float vv = v[j];
            int   vi = ii[j];
            if (vv > bv || (vv == bv && vi < bi)) { bv = vv; bi = vi; bs = j; }
        }
        used |= 1ull << bs;
        g_nn[(size_t)q * NK + r] = bi;
    }
}

// ------------------------- gather + max-pool + BN + ReLU ---------------------
// max_k relu(a*h_k + c) == relu(max(a*hmax + c, a*hmin + c))  (any sign of a)
__global__ __launch_bounds__(128) void gather_kernel(float* __restrict__ out) {
    __shared__ int nn[NK];
    const int q = blockIdx.x;
    const int tid = threadIdx.x;
    if (tid < NK) nn[tid] = g_nn[(size_t)q * NK + tid];
    __syncthreads();

    float mx[4] = {NEG_INF, NEG_INF, NEG_INF, NEG_INF};
    float mn[4] = {POS_INF, POS_INF, POS_INF, POS_INF};
#pragma unroll
    for (int n = 0; n < NK; n++) {
        const float* hp = g_h + (size_t)nn[n] * NO;
#pragma unroll
        for (int j = 0; j < 4; j++) {
            float v = hp[tid + j * 128];
            mx[j] = fmaxf(mx[j], v); mn[j] = fminf(mn[j], v);
        }
    }
    float* op = out + (size_t)q * NO;
#pragma unroll
    for (int j = 0; j < 4; j++) {
        int c = tid + j * 128;
        float a = g_a[c], cc = g_c[c];
        float o = fmaxf(fmaf(a, mx[j], cc), fmaf(a, mn[j], cc));
        op[c] = fmaxf(o, 0.0f);
    }
}

// ------------------------- launch --------------------------------------------
#define FPS_SMEM ((NP * 3 + NS + 16 + 16 + 1) * 4)
#define KNN_SMEM ((8 * 128 * 2 + 128 * 129 + 128 + 128 * 16 * 2 + 128) * 4)

extern "C" void kernel_launch(void* const* d_in, const int* in_sizes, int n_in,
                              void* d_out, int out_size) {
    (void)in_sizes; (void)n_in; (void)out_size;
    const float* features  = (const float*)d_in[0];
    const float* positions = (const float*)d_in[1];
    const int*   batch     = (const int*)d_in[2];
    const float* W         = (const float*)d_in[3];
    const float* bias      = (const float*)d_in[4];
    const float* gamma     = (const float*)d_in[5];
    const float* beta      = (const float*)d_in[6];

    float* out       = (float*)d_out;
    float* out_feat  = out;
    float* out_pos   = out + (size_t)NQ * NO;
    float* out_batch = out_pos + (size_t)NQ * 3;

    cudaFuncSetAttribute(fps_kernel, cudaFuncAttributeMaxDynamicSharedMemorySize, FPS_SMEM);
    cudaFuncSetAttribute(knn_kernel, cudaFuncAttributeMaxDynamicSharedMemorySize, KNN_SMEM);

    fps_kernel<<<NB, 512, FPS_SMEM>>>(positions, batch, out_pos, out_batch);
    xnorm_kernel<<<NPTS / 4, 128>>>(features);
    gemm_h_kernel<<<dim3(4, 512), 256>>>(features, W, bias);
    stats_partial_kernel<<<128, 512>>>();
    stats_final_kernel<<<1, 512>>>(gamma, beta);
    knn_kernel<<<dim3(8, SEG, NB), 256, KNN_SMEM>>>(features);
    merge_kernel<<<NQ / 256, 256>>>();
    gather_kernel<<<NQ, 128>>>(out_feat);
}

// round 7
// speedup vs baseline: 1.3899x; 1.1489x over previous
#include <cuda_runtime.h>
#include <cstdint>
#include <cstddef>

#define NB 16
#define NP 4096
#define NS 1024
#define NK 16
#define NF 256
#define NO 512
#define NPTS (NB*NP)
#define NQ   (NB*NS)
#define SEG  4
#define PSEG (NP/SEG)

#define POS_INF __int_as_float(0x7f800000)
#define NEG_INF __int_as_float(0xff800000)

typedef unsigned long long u64;

__device__ float g_h[(size_t)NPTS * NO];
__device__ float g_hn[NPTS];
__device__ int   g_fps[NQ];
__device__ float g_part[2 * 128 * NO];
__device__ float g_a[NO];
__device__ float g_c[NO];
__device__ float g_knnv[(size_t)NQ * SEG * NK];
__device__ int   g_knni[(size_t)NQ * SEG * NK];
__device__ int   g_nn[(size_t)NQ * NK];

// ---------------- f32x2 helpers (each half rounds exactly like scalar FFMA) --
__device__ __forceinline__ u64 dup2(float x) {
    u64 r;
    uint32_t b = __float_as_uint(x);
    asm("mov.b64 %0, {%1, %1};" : "=l"(r) : "r"(b));
    return r;
}
#define FMA2(acc, a, b) \
    asm("fma.rn.f32x2 %0, %1, %2, %0;" : "+l"(acc) : "l"(a), "l"(b))
__device__ __forceinline__ float2 unpack2(u64 v) {
    float2 r;
    asm("mov.b64 {%0, %1}, %2;" : "=f"(r.x), "=f"(r.y) : "l"(v));
    return r;
}

// ===================== K1: fused FPS + MLP-GEMM + xnorm ======================
// bid 0..15: FPS (one cloud each, scheduled in wave 1, hidden under GEMM).
// bid 16..2063: GEMM h = XW + b (bx = b&3, by = b>>2); bx==0 also folds
//               hn = 0.5*|x|^2 from the streamed A tiles.
#define FPS_SMEM_BYTES ((NP * 3 + NS + 8 + 8 + 1) * 4)
#define GEMM_SMEM_BYTES (2 * 2 * 8 * 128 * 4)   // 2 stages x (As+Bs)
#define FUSED_SMEM (FPS_SMEM_BYTES > GEMM_SMEM_BYTES ? FPS_SMEM_BYTES : GEMM_SMEM_BYTES)

__device__ void fps_body(char* smc, const float* __restrict__ positions,
                         const int* __restrict__ batch,
                         float* __restrict__ out_pos, float* __restrict__ out_batch,
                         int cloud) {
    float* spos  = (float*)smc;
    int*   sel   = (int*)(spos + NP * 3);
    float* rv    = (float*)(sel + NS);
    int*   ri    = (int*)(rv + 8);
    int*   slast = ri + 8;
    const int tid = threadIdx.x;
    const float* pos = positions + (size_t)cloud * NP * 3;
    for (int i = tid; i < NP * 3; i += 256) spos[i] = pos[i];
    __syncthreads();

    float px[16], py[16], pz[16], md[16];
#pragma unroll
    for (int j = 0; j < 16; j++) {
        int pt = tid + j * 256;
        px[j] = spos[pt * 3]; py[j] = spos[pt * 3 + 1]; pz[j] = spos[pt * 3 + 2];
        md[j] = POS_INF;
    }
    if (tid == 0) sel[0] = 0;
    int last = 0;
    const int lane = tid & 31, warp = tid >> 5;
    for (int it = 1; it < NS; it++) {
        float lx = spos[last * 3], ly = spos[last * 3 + 1], lz = spos[last * 3 + 2];
        float bv = NEG_INF; int bi = 0x7fffffff;
#pragma unroll
        for (int j = 0; j < 16; j++) {
            float dx = px[j] - lx, dy = py[j] - ly, dz = pz[j] - lz;
            float d = __fadd_rn(__fadd_rn(__fmul_rn(dx, dx), __fmul_rn(dy, dy)),
                                __fmul_rn(dz, dz));
            float m = fminf(md[j], d);
            md[j] = m;
            if (m > bv) { bv = m; bi = tid + j * 256; }   // j asc => idx asc
        }
#pragma unroll
        for (int off = 16; off > 0; off >>= 1) {
            float ov = __shfl_down_sync(0xffffffffu, bv, off);
            int   oi = __shfl_down_sync(0xffffffffu, bi, off);
            if (ov > bv || (ov == bv && oi < bi)) { bv = ov; bi = oi; }
        }
        if (lane == 0) { rv[warp] = bv; ri[warp] = bi; }
        __syncthreads();
        if (warp == 0) {
            float v = (lane < 8) ? rv[lane] : NEG_INF;
            int b = (lane < 8) ? ri[lane] : 0x7fffffff;
#pragma unroll
            for (int off = 4; off > 0; off >>= 1) {
                float ov = __shfl_down_sync(0xffffffffu, v, off);
                int   oi = __shfl_down_sync(0xffffffffu, b, off);
                if (ov > v || (ov == v && oi < b)) { v = ov; b = oi; }
            }
            if (lane == 0) { sel[it] = b; slast[0] = b; }
        }
        __syncthreads();
        last = slast[0];
    }
    for (int s = tid; s < NS; s += 256) {
        int loc = sel[s], g = cloud * NP + loc, oq = cloud * NS + s;
        g_fps[oq] = g;
        out_pos[oq * 3 + 0] = spos[loc * 3 + 0];
        out_pos[oq * 3 + 1] = spos[loc * 3 + 1];
        out_pos[oq * 3 + 2] = spos[loc * 3 + 2];
        out_batch[oq] = (float)batch[g];
    }
}

__global__ __launch_bounds__(256, 2) void fused_kernel(
    const float* __restrict__ A, const float* __restrict__ positions,
    const int* __restrict__ batch, const float* __restrict__ W,
    const float* __restrict__ bias,
    float* __restrict__ out_pos, float* __restrict__ out_batch) {
    extern __shared__ __align__(16) char smc[];
    if (blockIdx.x < 16) {
        fps_body(smc, positions, batch, out_pos, out_batch, blockIdx.x);
        return;
    }
    const int b = blockIdx.x - 16;
    const int bx = b & 3, by = b >> 2;
    float* As = (float*)smc;          // [2][8][128]
    float* Bs = As + 2 * 8 * 128;     // [2][8][128]
    const int tid = threadIdx.x;
    const int tx = tid & 15, ty = tid >> 4;
    const int arow = tid >> 1, half = tid & 1, acol = half * 4;
    const int brow = tid >> 5, bcol = (tid & 31) * 4;
    const float* aptr = A + (size_t)(by * 128 + arow) * NF + acol;
    const float* wbase = W + (size_t)brow * NO + bx * 128 + bcol;

    u64 acc2[8][4];
#pragma unroll
    for (int i = 0; i < 8; i++)
#pragma unroll
        for (int jp = 0; jp < 4; jp++) acc2[i][jp] = 0ull;
    float sq = 0.f;

    float4 av = *(const float4*)aptr;
    float4 bv = *(const float4*)wbase;
    for (int kb = 0; kb < 32; kb++) {
        float* Asb = As + (kb & 1) * 1024;
        float* Bsb = Bs + (kb & 1) * 1024;
        Asb[(acol + 0) * 128 + arow] = av.x;
        Asb[(acol + 1) * 128 + arow] = av.y;
        Asb[(acol + 2) * 128 + arow] = av.z;
        Asb[(acol + 3) * 128 + arow] = av.w;
        *(float4*)&Bsb[brow * 128 + bcol] = bv;
        if (bx == 0) {
            sq = fmaf(av.x, av.x, sq); sq = fmaf(av.y, av.y, sq);
            sq = fmaf(av.z, av.z, sq); sq = fmaf(av.w, av.w, sq);
        }
        __syncthreads();
        if (kb < 31) {
            av = *(const float4*)(aptr + (kb + 1) * 8);
            bv = *(const float4*)(wbase + (size_t)(kb + 1) * 8 * NO);
        }
#pragma unroll
        for (int k = 0; k < 8; k++) {
            float4 a0 = *(const float4*)&Asb[k * 128 + ty * 8];
            float4 a1 = *(const float4*)&Asb[k * 128 + ty * 8 + 4];
            const u64* bp = (const u64*)&Bsb[k * 128 + tx * 8];
            u64 b2[4] = {bp[0], bp[1], bp[2], bp[3]};
            u64 ad[8] = {dup2(a0.x), dup2(a0.y), dup2(a0.z), dup2(a0.w),
                         dup2(a1.x), dup2(a1.y), dup2(a1.z), dup2(a1.w)};
#pragma unroll
            for (int i = 0; i < 8; i++)
#pragma unroll
                for (int jp = 0; jp < 4; jp++)
                    FMA2(acc2[i][jp], ad[i], b2[jp]);
        }
    }

    if (bx == 0) {
        float o = __shfl_xor_sync(0xffffffffu, sq, 1);
        if (half == 0) g_hn[by * 128 + arow] = 0.5f * (sq + o);
    }

    const int ccol = bx * 128 + tx * 8;
    const int crow = by * 128 + ty * 8;
    float4 bb0 = *(const float4*)(bias + ccol);
    float4 bb1 = *(const float4*)(bias + ccol + 4);
#pragma unroll
    for (int i = 0; i < 8; i++) {
        float2 p0 = unpack2(acc2[i][0]), p1 = unpack2(acc2[i][1]);
        float2 p2 = unpack2(acc2[i][2]), p3 = unpack2(acc2[i][3]);
        float4 o0, o1;
        o0.x = p0.x + bb0.x; o0.y = p0.y + bb0.y;
        o0.z = p1.x + bb0.z; o0.w = p1.y + bb0.w;
        o1.x = p2.x + bb1.x; o1.y = p2.y + bb1.y;
        o1.z = p3.x + bb1.z; o1.w = p3.y + bb1.w;
        *(float4*)(g_h + (size_t)(crow + i) * NO + ccol) = o0;
        *(float4*)(g_h + (size_t)(crow + i) * NO + ccol + 4) = o1;
    }
}

// ===================== BN stats =====================
__global__ __launch_bounds__(512) void stats_partial_kernel() {
    int c = threadIdx.x, blk = blockIdx.x;
    float s = 0.f, s2 = 0.f;
    int r0 = blk * 512;
    for (int r = 0; r < 512; r++) {
        float v = g_h[(size_t)(r0 + r) * NO + c];
        s += v; s2 = fmaf(v, v, s2);
    }
    g_part[blk * NO + c] = s;
    g_part[128 * NO + blk * NO + c] = s2;
}
__global__ __launch_bounds__(512) void stats_final_kernel(const float* __restrict__ gamma,
                                                          const float* __restrict__ beta) {
    int c = threadIdx.x;
    float s = 0.f, s2 = 0.f;
    for (int b = 0; b < 128; b++) { s += g_part[b * NO + c]; s2 += g_part[128 * NO + b * NO + c]; }
    float inv = 1.0f / (float)NPTS;
    float mu = s * inv, var = s2 * inv - mu * mu;
    float a = gamma[c] * rsqrtf(var + 1e-5f);
    g_a[c] = a; g_c[c] = beta[c] - mu * a;
}

// ===================== KNN: f32x2 score GEMM + top-16, pipelined =============
// smem: Qs[2][8][128], Xs[2][8][128], Sc[128*129], hn[128], topv/topi[128*16]
#define K_QS 0
#define K_XS (K_QS + 2*8*128*4)
#define K_SC (K_XS + 2*8*128*4)
#define K_HN (K_SC + 128*129*4)
#define K_TV (K_HN + 128*4)
#define K_TI (K_TV + 128*NK*4)
#define KNN_SMEM (K_TI + 128*NK*4)   // 99328 B -> occ 2

__global__ __launch_bounds__(256, 2) void knn_kernel(const float* __restrict__ feat) {
    extern __shared__ __align__(16) char smc[];
    float* Qs   = (float*)(smc + K_QS);
    float* Xs   = (float*)(smc + K_XS);
    float* Sc   = (float*)(smc + K_SC);
    float* hn_s = (float*)(smc + K_HN);
    float* topv = (float*)(smc + K_TV);
    int*   topi = (int*)(smc + K_TI);

    const int qt = blockIdx.x, sg = blockIdx.y, cloud = blockIdx.z;
    const int tid = threadIdx.x;
    const int tx = tid & 15, ty = tid >> 4;
    const int arow = tid >> 1, acol = (tid & 1) * 4;

    const int qr = g_fps[cloud * NS + qt * 128 + arow];
    const float* qptr = feat + (size_t)qr * NF + acol;

    if (tid < 128) {
#pragma unroll
        for (int r = 0; r < NK; r++) {
            topv[tid * NK + r] = NEG_INF;
            topi[tid * NK + r] = 0x7fffffff;
        }
    }
    const int xcloudbase = cloud * NP + sg * PSEG;
    __syncthreads();

    for (int t = 0; t < PSEG / 128; t++) {
        const int xbase = xcloudbase + t * 128;
        if (tid < 128) hn_s[tid] = g_hn[xbase + tid];
        const float* xptr = feat + (size_t)(xbase + arow) * NF + acol;

        u64 acc2[8][4];
#pragma unroll
        for (int i = 0; i < 8; i++)
#pragma unroll
            for (int jp = 0; jp < 4; jp++) acc2[i][jp] = 0ull;

        float4 qv = *(const float4*)qptr;
        float4 xv = *(const float4*)xptr;
        for (int kb = 0; kb < 32; kb++) {
            float* Qsb = Qs + (kb & 1) * 1024;
            float* Xsb = Xs + (kb & 1) * 1024;
            Qsb[(acol + 0) * 128 + arow] = qv.x;
            Qsb[(acol + 1) * 128 + arow] = qv.y;
            Qsb[(acol + 2) * 128 + arow] = qv.z;
            Qsb[(acol + 3) * 128 + arow] = qv.w;
            Xsb[(acol + 0) * 128 + arow] = xv.x;
            Xsb[(acol + 1) * 128 + arow] = xv.y;
            Xsb[(acol + 2) * 128 + arow] = xv.z;
            Xsb[(acol + 3) * 128 + arow] = xv.w;
            __syncthreads();
            if (kb < 31) {
                qv = *(const float4*)(qptr + (kb + 1) * 8);
                xv = *(const float4*)(xptr + (kb + 1) * 8);
            }
#pragma unroll
            for (int k = 0; k < 8; k++) {
                float4 a0 = *(const float4*)&Qsb[k * 128 + ty * 8];
                float4 a1 = *(const float4*)&Qsb[k * 128 + ty * 8 + 4];
                const u64* bp = (const u64*)&Xsb[k * 128 + tx * 8];
                u64 b2[4] = {bp[0], bp[1], bp[2], bp[3]};
                u64 ad[8] = {dup2(a0.x), dup2(a0.y), dup2(a0.z), dup2(a0.w),
                             dup2(a1.x), dup2(a1.y), dup2(a1.z), dup2(a1.w)};
#pragma unroll
                for (int i = 0; i < 8; i++)
#pragma unroll
                    for (int jp = 0; jp < 4; jp++)
                        FMA2(acc2[i][jp], ad[i], b2[jp]);
            }
        }
        __syncthreads();   // all reads of stage buffers done before next-tile STS

#pragma unroll
        for (int i = 0; i < 8; i++) {
#pragma unroll
            for (int jp = 0; jp < 4; jp++) {
                float2 p = unpack2(acc2[i][jp]);
                Sc[(ty * 8 + i) * 129 + tx * 8 + jp * 2]     = p.x;
                Sc[(ty * 8 + i) * 129 + tx * 8 + jp * 2 + 1] = p.y;
            }
        }
        __syncthreads();

        if (tid < 128) {   // running top-16, (score desc, idx asc)
            const float* scr = Sc + tid * 129;
            float* tv = topv + tid * NK;
            int*   ti = topi + tid * NK;
            float th = tv[NK - 1];
            int  thi = ti[NK - 1];
            for (int p = 0; p < 128; p++) {
                float s = scr[p] - hn_s[p];
                int gi = xbase + p;
                if (s > th || (s == th && gi < thi)) {
                    int r = NK - 1;
                    while (r > 0) {
                        float pv = tv[r - 1];
                        int   pi = ti[r - 1];
                        if (s > pv || (s == pv && gi < pi)) {
                            tv[r] = pv; ti[r] = pi; r--;
                        } else break;
                    }
                    tv[r] = s; ti[r] = gi;
                    th = tv[NK - 1]; thi = ti[NK - 1];
                }
            }
        }
        __syncthreads();
    }

    if (tid < 128) {
        int q = cloud * NS + qt * 128 + tid;
#pragma unroll
        for (int r = 0; r < NK; r++) {
            g_knnv[((size_t)q * SEG + sg) * NK + r] = topv[tid * NK + r];
            g_knni[((size_t)q * SEG + sg) * NK + r] = topi[tid * NK + r];
        }
    }
}

// ===================== merge + gather =====================
__global__ __launch_bounds__(256) void merge_kernel() {
    int q = blockIdx.x * 256 + threadIdx.x;
    if (q >= NQ) return;
    const float* v  = g_knnv + (size_t)q * SEG * NK;
    const int*   ii = g_knni + (size_t)q * SEG * NK;
    unsigned long long used = 0ull;
    for (int r = 0; r < NK; r++) {
        float bv = NEG_INF; int bi = 0x7fffffff, bs = 0;
        for (int j = 0; j < SEG * NK; j++) {
            if ((used >> j) & 1ull) continue;
            float vv = v[j]; int vi = ii[j];
            if (vv > bv || (vv == bv && vi < bi)) { bv = vv; bi = vi; bs = j; }
        }
        used |= 1ull << bs;
        g_nn[(size_t)q * NK + r] = bi;
    }
}

__global__ __launch_bounds__(128) void gather_kernel(float* __restrict__ out) {
    __shared__ int nn[NK];
    const int q = blockIdx.x, tid = threadIdx.x;
    if (tid < NK) nn[tid] = g_nn[(size_t)q * NK + tid];
    __syncthreads();
    float mx[4] = {NEG_INF, NEG_INF, NEG_INF, NEG_INF};
    float mn[4] = {POS_INF, POS_INF, POS_INF, POS_INF};
#pragma unroll
    for (int n = 0; n < NK; n++) {
        const float* hp = g_h + (size_t)nn[n] * NO;
#pragma unroll
        for (int j = 0; j < 4; j++) {
            float v = hp[tid + j * 128];
            mx[j] = fmaxf(mx[j], v); mn[j] = fminf(mn[j], v);
        }
    }
    float* op = out + (size_t)q * NO;
#pragma unroll
    for (int j = 0; j < 4; j++) {
        int c = tid + j * 128;
        float a = g_a[c], cc = g_c[c];
        float o = fmaxf(fmaf(a, mx[j], cc), fmaf(a, mn[j], cc));
        op[c] = fmaxf(o, 0.0f);
    }
}

// ===================== launch =====================
extern "C" void kernel_launch(void* const* d_in, const int* in_sizes, int n_in,
                              void* d_out, int out_size) {
    (void)in_sizes; (void)n_in; (void)out_size;
    const float* features  = (const float*)d_in[0];
    const float* positions = (const float*)d_in[1];
    const int*   batch     = (const int*)d_in[2];
    const float* W         = (const float*)d_in[3];
    const float* bias      = (const float*)d_in[4];
    const float* gamma     = (const float*)d_in[5];
    const float* beta      = (const float*)d_in[6];

    float* out       = (float*)d_out;
    float* out_feat  = out;
    float* out_pos   = out + (size_t)NQ * NO;
    float* out_batch = out_pos + (size_t)NQ * 3;

    cudaFuncSetAttribute(fused_kernel, cudaFuncAttributeMaxDynamicSharedMemorySize, FUSED_SMEM);
    cudaFuncSetAttribute(knn_kernel, cudaFuncAttributeMaxDynamicSharedMemorySize, KNN_SMEM);

    fused_kernel<<<16 + 2048, 256, FUSED_SMEM>>>(features, positions, batch, W, bias,
                                                 out_pos, out_batch);
    stats_partial_kernel<<<128, 512>>>();
    stats_final_kernel<<<1, 512>>>(gamma, beta);
    knn_kernel<<<dim3(8, SEG, NB), 256, KNN_SMEM>>>(features);   // 4th launch -> ncu
    merge_kernel<<<NQ / 256, 256>>>();
    gather_kernel<<<NQ, 128>>>(out_feat);
}